// round 14
// baseline (speedup 1.0000x reference)
#include <cuda_runtime.h>

// NeuralODE: encoder -> 99 RK4 steps -> decoder at every timestep.
// E=2 elements/thread + MUFU.TANH (R11 = 2338us). THIS REV: attack latency
// exposure. Grid caps warps at 1024 (6.9/SM) so registers are free until
// ~250: __launch_bounds__(128,1) unlocks the full file, and ode_f2/decode2
// are explicitly software-pipelined (row i+1's weights prefetched before
// row i's tanh; wo2 row loaded before the tanh it consumes).

#define HID 50
#define LAT 16

typedef unsigned long long u64;

__device__ __forceinline__ u64 pk2(float a, float b) {
    u64 v; asm("mov.b64 %0, {%1,%2};" : "=l"(v) : "f"(a), "f"(b)); return v;
}
__device__ __forceinline__ float2 up2(u64 v) {
    float2 r; asm("mov.b64 {%0,%1}, %2;" : "=f"(r.x), "=f"(r.y) : "l"(v)); return r;
}
__device__ __forceinline__ u64 ffma2(u64 a, u64 b, u64 c) {
    u64 d; asm("fma.rn.f32x2 %0, %1, %2, %3;" : "=l"(d) : "l"(a), "l"(b), "l"(c)); return d;
}
__device__ __forceinline__ u64 fmul2(u64 a, u64 b) {
    u64 d; asm("mul.rn.f32x2 %0, %1, %2;" : "=l"(d) : "l"(a), "l"(b)); return d;
}
__device__ __forceinline__ u64 fadd2(u64 a, u64 b) {
    u64 d; asm("add.rn.f32x2 %0, %1, %2;" : "=l"(d) : "l"(a), "l"(b)); return d;
}

// Hardware tanh (MUFU.TANH): 1 op, ~2^-11 max abs err.
__device__ __forceinline__ float tanh_hw(float x) {
    float r; asm("tanh.approx.f32 %0, %1;" : "=f"(r) : "f"(x)); return r;
}

struct __align__(16) SW {
    float wo1t[HID * LAT];  // wo1t[i*16+k] = Wo1[k][i]
    float wo2 [HID * LAT];  // Wo2[i][j], row-major
    float we2 [HID * LAT];  // We2[i][k], row-major
    float wd1t[HID * LAT];  // wd1t[i*16+k] = Wd1[k][i]
    float bo2[LAT];
    float be2[LAT];
    float bo1[HID];
    float be1[HID];
    float bd1[HID];
    float we1a[HID];        // We1[0][i]
    float we1b[HID];        // We1[1][i]
    float wd2[HID];
    float dt[128];
    float bd2;
};

// dot of 16-dim packed z with a weight row already in registers
__device__ __forceinline__ float rdot(const u64 zp[8], ulonglong2 w0, ulonglong2 w1,
                                      ulonglong2 w2, ulonglong2 w3) {
    u64 a0 = fmul2(zp[0], w0.x);
    u64 a1 = fmul2(zp[1], w0.y);
    a0 = ffma2(zp[2], w1.x, a0);
    a1 = ffma2(zp[3], w1.y, a1);
    a0 = ffma2(zp[4], w2.x, a0);
    a1 = ffma2(zp[5], w2.y, a1);
    a0 = ffma2(zp[6], w3.x, a0);
    a1 = ffma2(zp[7], w3.y, a1);
    float2 p = up2(fadd2(a0, a1));
    return p.x + p.y;
}

// k = tanh(z@Wo1 + bo1) @ Wo2 + bo2  for two elements sharing weight loads.
// Software-pipelined: row i+1's wo1t prefetched before row i's tanh;
// wo2 row loaded before the tanh it consumes.
__device__ __forceinline__ void ode_f2(const u64 zA[8], const u64 zB[8],
                                       u64 kA[8], u64 kB[8], const SW& s) {
    const u64* bo2p = (const u64*)s.bo2;
#pragma unroll
    for (int j = 0; j < 8; j++) { kA[j] = bo2p[j]; kB[j] = bo2p[j]; }

    const ulonglong2* w = (const ulonglong2*)s.wo1t;
    ulonglong2 p0 = w[0], p1 = w[1], p2 = w[2], p3 = w[3];
#pragma unroll 10
    for (int i = 0; i < HID; i++) {
        ulonglong2 w0 = p0, w1 = p1, w2 = p2, w3 = p3;
        // prefetch next row (wraps to row 0 on last iter; harmless)
        const ulonglong2* wn = (const ulonglong2*)(s.wo1t + ((i + 1) % HID) * LAT);
        p0 = wn[0]; p1 = wn[1]; p2 = wn[2]; p3 = wn[3];
        // load wo2 row BEFORE tanh (independent of the dot)
        const ulonglong2* v = (const ulonglong2*)(s.wo2 + i * LAT);
        ulonglong2 v0 = v[0], v1 = v[1], v2 = v[2], v3 = v[3];

        float b1 = s.bo1[i];
        float hA = tanh_hw(rdot(zA, w0, w1, w2, w3) + b1);
        float hB = tanh_hw(rdot(zB, w0, w1, w2, w3) + b1);
        u64 hA2 = pk2(hA, hA), hB2 = pk2(hB, hB);

        kA[0] = ffma2(hA2, v0.x, kA[0]);
        kA[1] = ffma2(hA2, v0.y, kA[1]);
        kA[2] = ffma2(hA2, v1.x, kA[2]);
        kA[3] = ffma2(hA2, v1.y, kA[3]);
        kA[4] = ffma2(hA2, v2.x, kA[4]);
        kA[5] = ffma2(hA2, v2.y, kA[5]);
        kA[6] = ffma2(hA2, v3.x, kA[6]);
        kA[7] = ffma2(hA2, v3.y, kA[7]);
        kB[0] = ffma2(hB2, v0.x, kB[0]);
        kB[1] = ffma2(hB2, v0.y, kB[1]);
        kB[2] = ffma2(hB2, v1.x, kB[2]);
        kB[3] = ffma2(hB2, v1.y, kB[3]);
        kB[4] = ffma2(hB2, v2.x, kB[4]);
        kB[5] = ffma2(hB2, v2.y, kB[5]);
        kB[6] = ffma2(hB2, v3.x, kB[6]);
        kB[7] = ffma2(hB2, v3.y, kB[7]);
    }
}

// y = relu(z@Wd1 + bd1) @ Wd2 + bd2, software-pipelined like ode_f2.
__device__ __forceinline__ float2 decode2(const u64 zA[8], const u64 zB[8], const SW& s) {
    float yA = s.bd2, yB = s.bd2;
    const ulonglong2* w = (const ulonglong2*)s.wd1t;
    ulonglong2 p0 = w[0], p1 = w[1], p2 = w[2], p3 = w[3];
#pragma unroll 10
    for (int i = 0; i < HID; i++) {
        ulonglong2 w0 = p0, w1 = p1, w2 = p2, w3 = p3;
        const ulonglong2* wn = (const ulonglong2*)(s.wd1t + ((i + 1) % HID) * LAT);
        p0 = wn[0]; p1 = wn[1]; p2 = wn[2]; p3 = wn[3];
        float hA = fmaxf(rdot(zA, w0, w1, w2, w3) + s.bd1[i], 0.0f);
        float hB = fmaxf(rdot(zB, w0, w1, w2, w3) + s.bd1[i], 0.0f);
        float wd = s.wd2[i];
        yA = fmaf(hA, wd, yA);
        yB = fmaf(hB, wd, yB);
    }
    return make_float2(yA, yB);
}

__global__ void __launch_bounds__(128, 1)
node_kernel(const float* __restrict__ x0, const float* __restrict__ t,
            const float* __restrict__ We1, const float* __restrict__ be1,
            const float* __restrict__ We2, const float* __restrict__ be2,
            const float* __restrict__ Wo1, const float* __restrict__ bo1,
            const float* __restrict__ Wo2, const float* __restrict__ bo2,
            const float* __restrict__ Wd1, const float* __restrict__ bd1,
            const float* __restrict__ Wd2, const float* __restrict__ bd2,
            float* __restrict__ out, int Bn, int Tn) {
    __shared__ SW s;
    int tid = threadIdx.x;

    for (int idx = tid; idx < HID * LAT; idx += blockDim.x) {
        int i = idx >> 4, k = idx & 15;
        s.wo1t[idx] = Wo1[k * HID + i];
        s.wd1t[idx] = Wd1[k * HID + i];
        s.wo2[idx]  = Wo2[idx];
        s.we2[idx]  = We2[idx];
    }
    for (int idx = tid; idx < HID; idx += blockDim.x) {
        s.bo1[idx]  = bo1[idx];
        s.be1[idx]  = be1[idx];
        s.bd1[idx]  = bd1[idx];
        s.we1a[idx] = We1[idx];
        s.we1b[idx] = We1[HID + idx];
        s.wd2[idx]  = Wd2[idx];
    }
    for (int idx = tid; idx < LAT; idx += blockDim.x) {
        s.bo2[idx] = bo2[idx];
        s.be2[idx] = be2[idx];
    }
    for (int idx = tid; idx < Tn - 1 && idx < 128; idx += blockDim.x)
        s.dt[idx] = t[idx + 1] - t[idx];
    if (tid == 0) s.bd2 = bd2[0];
    __syncthreads();

    int bA = blockIdx.x * 256 + tid;
    int bB = bA + 128;
    if (bA >= Bn) return;
    bool hasB = (bB < Bn);

    // ---------- Encoder for both elements (shared weight loads) ----------
    float2 xA = ((const float2*)x0)[bA];
    float2 xB = hasB ? ((const float2*)x0)[bB] : make_float2(0.f, 0.f);
    u64 zA[8], zB[8];
    {
        const u64* be2p = (const u64*)s.be2;
#pragma unroll
        for (int j = 0; j < 8; j++) { zA[j] = be2p[j]; zB[j] = be2p[j]; }
#pragma unroll 10
        for (int i = 0; i < HID; i++) {
            float w1a = s.we1a[i], w1b = s.we1b[i], b1 = s.be1[i];
            float hA = fmaxf(fmaf(xA.y, w1b, fmaf(xA.x, w1a, b1)), 0.0f);
            float hB = fmaxf(fmaf(xB.y, w1b, fmaf(xB.x, w1a, b1)), 0.0f);
            u64 hA2 = pk2(hA, hA), hB2 = pk2(hB, hB);
            const ulonglong2* w = (const ulonglong2*)(s.we2 + i * LAT);
#pragma unroll
            for (int j = 0; j < 4; j++) {
                ulonglong2 ww = w[j];
                zA[2 * j]     = ffma2(hA2, ww.x, zA[2 * j]);
                zA[2 * j + 1] = ffma2(hA2, ww.y, zA[2 * j + 1]);
                zB[2 * j]     = ffma2(hB2, ww.x, zB[2 * j]);
                zB[2 * j + 1] = ffma2(hB2, ww.y, zB[2 * j + 1]);
            }
        }
    }

    {
        float2 y = decode2(zA, zB, s);
        out[bA] = y.x;
        if (hasB) out[bB] = y.y;
    }

    // ---------- RK4 time stepping (stages fully unrolled) ----------
    for (int st = 0; st < Tn - 1; ++st) {
        float dt = s.dt[st];
        float h6 = dt * (1.0f / 6.0f);
        float h3 = dt * (1.0f / 3.0f);
        float hf = dt * 0.5f;
        u64 c6 = pk2(h6, h6), c3 = pk2(h3, h3), c2 = pk2(hf, hf), c1 = pk2(dt, dt);

        u64 znA[8], ztA[8], kkA[8];
        u64 znB[8], ztB[8], kkB[8];

        // stage 1
        ode_f2(zA, zB, kkA, kkB, s);
#pragma unroll
        for (int j = 0; j < 8; j++) {
            znA[j] = ffma2(c6, kkA[j], zA[j]);
            ztA[j] = ffma2(c2, kkA[j], zA[j]);
            znB[j] = ffma2(c6, kkB[j], zB[j]);
            ztB[j] = ffma2(c2, kkB[j], zB[j]);
        }
        // stage 2
        ode_f2(ztA, ztB, kkA, kkB, s);
#pragma unroll
        for (int j = 0; j < 8; j++) {
            znA[j] = ffma2(c3, kkA[j], znA[j]);
            ztA[j] = ffma2(c2, kkA[j], zA[j]);
            znB[j] = ffma2(c3, kkB[j], znB[j]);
            ztB[j] = ffma2(c2, kkB[j], zB[j]);
        }
        // stage 3
        ode_f2(ztA, ztB, kkA, kkB, s);
#pragma unroll
        for (int j = 0; j < 8; j++) {
            znA[j] = ffma2(c3, kkA[j], znA[j]);
            ztA[j] = ffma2(c1, kkA[j], zA[j]);
            znB[j] = ffma2(c3, kkB[j], znB[j]);
            ztB[j] = ffma2(c1, kkB[j], zB[j]);
        }
        // stage 4
        ode_f2(ztA, ztB, kkA, kkB, s);
#pragma unroll
        for (int j = 0; j < 8; j++) {
            zA[j] = ffma2(c6, kkA[j], znA[j]);
            zB[j] = ffma2(c6, kkB[j], znB[j]);
        }

        float2 y = decode2(zA, zB, s);
        size_t base = (size_t)(st + 1) * Bn;
        out[base + bA] = y.x;
        if (hasB) out[base + bB] = y.y;
    }
}

extern "C" void kernel_launch(void* const* d_in, const int* in_sizes, int n_in,
                              void* d_out, int out_size) {
    const float* x0  = (const float*)d_in[0];
    const float* t   = (const float*)d_in[1];
    const float* We1 = (const float*)d_in[2];
    const float* be1 = (const float*)d_in[3];
    const float* We2 = (const float*)d_in[4];
    const float* be2 = (const float*)d_in[5];
    const float* Wo1 = (const float*)d_in[6];
    const float* bo1 = (const float*)d_in[7];
    const float* Wo2 = (const float*)d_in[8];
    const float* bo2 = (const float*)d_in[9];
    const float* Wd1 = (const float*)d_in[10];
    const float* bd1 = (const float*)d_in[11];
    const float* Wd2 = (const float*)d_in[12];
    const float* bd2 = (const float*)d_in[13];

    int Bn = in_sizes[0] / 2;   // x0 is (B, 2)
    int Tn = in_sizes[1];       // t is (T,)

    int threads = 128;
    int blocks = (Bn + 255) / 256;   // 2 elements per thread
    node_kernel<<<blocks, threads>>>(x0, t, We1, be1, We2, be2, Wo1, bo1,
                                     Wo2, bo2, Wd1, bd1, Wd2, bd2,
                                     (float*)d_out, Bn, Tn);
}

// round 16
// speedup vs baseline: 2.0207x; 2.0207x over previous
#include <cuda_runtime.h>
#include <cuda_bf16.h>
#include <cstdint>

// NeuralODE via mma.sync (HMMA, no 'a'-feature needed). Warp = 32 elements.
// All state kept in m16n8 D-fragment layout; D-frag of layer1 == A-frag of
// layer2 (zero-shuffle chaining). bf16 hi/lo split, 3 MMA terms per GEMM.

#define HID 50
#define LAT 16
#define NT1 7   // layer1 N-tiles (56 >= 50)
#define KT2 4   // layer2 K-tiles (64 >= 56)

struct SM {
    uint4 B1[NT1][32];       // Wo1 frags {hi0,hi1,lo0,lo1}
    uint4 BD1[NT1][32];      // Wd1 frags
    uint4 B2[KT2][2][32];    // Wo2 frags [ktile][ntile][lane]
    float zst[4][32][16];    // encoder->fragment staging per warp
    float bo1p[56], bd1p[56], wd2p[56];
    float bo2[16], be2[16];
    float we2[HID * 16], be1[HID], w1a[HID], w1b[HID];
    float dt[128];
    float bd2;
};

__device__ __forceinline__ float tanh_hw(float x) {
    float r; asm("tanh.approx.f32 %0, %1;" : "=f"(r) : "f"(x)); return r;
}
__device__ __forceinline__ float rbf(float x) {
    return __bfloat162float(__float2bfloat16_rn(x));
}
// pack two f32 -> bf16x2, low half = a, high half = b
__device__ __forceinline__ uint32_t pkhi(float a, float b) {
    uint32_t r;
    asm("cvt.rn.bf16x2.f32 %0, %1, %2;" : "=r"(r) : "f"(b), "f"(a));
    return r;
}
__device__ __forceinline__ uint32_t pklo(float a, float b) {
    return pkhi(a - rbf(a), b - rbf(b));
}
__device__ __forceinline__ void mma16816(float d[4], const uint32_t a[4],
                                         uint32_t b0, uint32_t b1) {
    asm volatile(
        "mma.sync.aligned.m16n8k16.row.col.f32.bf16.bf16.f32 "
        "{%0,%1,%2,%3}, {%4,%5,%6,%7}, {%8,%9}, {%0,%1,%2,%3};"
        : "+f"(d[0]), "+f"(d[1]), "+f"(d[2]), "+f"(d[3])
        : "r"(a[0]), "r"(a[1]), "r"(a[2]), "r"(a[3]), "r"(b0), "r"(b1));
}

// A-frags (hi+lo) from 16 f32 in D-layout: idx = m*8 + nt2*4 + j
__device__ __forceinline__ void build_a(const float z[16],
                                        uint32_t ah[2][4], uint32_t al[2][4]) {
#pragma unroll
    for (int m = 0; m < 2; m++) {
        const float* p = z + m * 8;
        ah[m][0] = pkhi(p[0], p[1]); al[m][0] = pklo(p[0], p[1]);
        ah[m][1] = pkhi(p[2], p[3]); al[m][1] = pklo(p[2], p[3]);
        ah[m][2] = pkhi(p[4], p[5]); al[m][2] = pklo(p[4], p[5]);
        ah[m][3] = pkhi(p[6], p[7]); al[m][3] = pklo(p[6], p[7]);
    }
}

// layer1: u[m][nt][4] = Z[32x16] @ W[16x56] (3-term compensated)
__device__ __forceinline__ void layer1(const float z[16], float u[2][NT1][4],
                                       const uint4 (*Bfr)[32], int lane) {
    uint32_t ah[2][4], al[2][4];
    build_a(z, ah, al);
#pragma unroll
    for (int nt = 0; nt < NT1; nt++) {
        uint4 b = Bfr[nt][lane];
#pragma unroll
        for (int m = 0; m < 2; m++) {
            float d[4] = {0.f, 0.f, 0.f, 0.f};
            mma16816(d, ah[m], b.x, b.y);
            mma16816(d, ah[m], b.z, b.w);
            mma16816(d, al[m], b.x, b.y);
            u[m][nt][0] = d[0]; u[m][nt][1] = d[1];
            u[m][nt][2] = d[2]; u[m][nt][3] = d[3];
        }
    }
}

// f(z) in fragment space: kk = tanh(z@Wo1+bo1)@Wo2 + bo2
__device__ __forceinline__ void f_eval(const float z[16], float kk[16],
                                       const SM& s, int lane, int lq,
                                       const float bo2c[4]) {
    float u[2][NT1][4];
    layer1(z, u, s.B1, lane);
    // tanh in place (pad cols have u=0, bo1p=0 -> h=0)
#pragma unroll
    for (int nt = 0; nt < NT1; nt++) {
        float b0 = s.bo1p[nt * 8 + lq * 2];
        float b1 = s.bo1p[nt * 8 + lq * 2 + 1];
#pragma unroll
        for (int m = 0; m < 2; m++) {
            u[m][nt][0] = tanh_hw(u[m][nt][0] + b0);
            u[m][nt][1] = tanh_hw(u[m][nt][1] + b1);
            u[m][nt][2] = tanh_hw(u[m][nt][2] + b0);
            u[m][nt][3] = tanh_hw(u[m][nt][3] + b1);
        }
    }
    float d2[2][2][4] = {};
#pragma unroll
    for (int kt = 0; kt < KT2; kt++) {
        uint32_t ah[2][4], al[2][4];
        int na = 2 * kt, nb = 2 * kt + 1;
#pragma unroll
        for (int m = 0; m < 2; m++) {
            ah[m][0] = pkhi(u[m][na][0], u[m][na][1]);
            al[m][0] = pklo(u[m][na][0], u[m][na][1]);
            ah[m][1] = pkhi(u[m][na][2], u[m][na][3]);
            al[m][1] = pklo(u[m][na][2], u[m][na][3]);
            if (nb < NT1) {
                ah[m][2] = pkhi(u[m][nb][0], u[m][nb][1]);
                al[m][2] = pklo(u[m][nb][0], u[m][nb][1]);
                ah[m][3] = pkhi(u[m][nb][2], u[m][nb][3]);
                al[m][3] = pklo(u[m][nb][2], u[m][nb][3]);
            } else {
                ah[m][2] = 0u; al[m][2] = 0u; ah[m][3] = 0u; al[m][3] = 0u;
            }
        }
#pragma unroll
        for (int n2 = 0; n2 < 2; n2++) {
            uint4 b = s.B2[kt][n2][lane];
#pragma unroll
            for (int m = 0; m < 2; m++) {
                mma16816(d2[m][n2], ah[m], b.x, b.y);
                mma16816(d2[m][n2], ah[m], b.z, b.w);
                mma16816(d2[m][n2], al[m], b.x, b.y);
            }
        }
    }
#pragma unroll
    for (int m = 0; m < 2; m++)
#pragma unroll
        for (int n2 = 0; n2 < 2; n2++) {
            kk[m * 8 + n2 * 4 + 0] = d2[m][n2][0] + bo2c[n2 * 2 + 0];
            kk[m * 8 + n2 * 4 + 1] = d2[m][n2][1] + bo2c[n2 * 2 + 1];
            kk[m * 8 + n2 * 4 + 2] = d2[m][n2][2] + bo2c[n2 * 2 + 0];
            kk[m * 8 + n2 * 4 + 3] = d2[m][n2][3] + bo2c[n2 * 2 + 1];
        }
}

// decoder: y rows via layer1(Wd1) + relu-dot(wd2) + cross-lane reduce
__device__ __forceinline__ void dec_eval(const float z[16], const SM& s,
                                         int lane, int lq, int lr,
                                         float* out, int wbase, int Bn,
                                         size_t tbase) {
    float u[2][NT1][4];
    layer1(z, u, s.BD1, lane);
    float y[2][2] = {};
#pragma unroll
    for (int nt = 0; nt < NT1; nt++) {
        int c0 = nt * 8 + lq * 2;
        float b0 = s.bd1p[c0], b1 = s.bd1p[c0 + 1];
        float w0 = s.wd2p[c0], w1 = s.wd2p[c0 + 1];
#pragma unroll
        for (int m = 0; m < 2; m++) {
            y[m][0] = fmaf(fmaxf(u[m][nt][0] + b0, 0.f), w0, y[m][0]);
            y[m][0] = fmaf(fmaxf(u[m][nt][1] + b1, 0.f), w1, y[m][0]);
            y[m][1] = fmaf(fmaxf(u[m][nt][2] + b0, 0.f), w0, y[m][1]);
            y[m][1] = fmaf(fmaxf(u[m][nt][3] + b1, 0.f), w1, y[m][1]);
        }
    }
#pragma unroll
    for (int m = 0; m < 2; m++)
#pragma unroll
        for (int h = 0; h < 2; h++) {
            float v = y[m][h];
            v += __shfl_xor_sync(0xffffffffu, v, 1);
            v += __shfl_xor_sync(0xffffffffu, v, 2);
            if (lq == 0) {
                int row = m * 16 + h * 8 + lr;
                int elem = wbase + row;
                if (elem < Bn) out[tbase + elem] = v + s.bd2;
            }
        }
}

__global__ void __launch_bounds__(128)
node_kernel(const float* __restrict__ x0, const float* __restrict__ t,
            const float* __restrict__ We1, const float* __restrict__ be1,
            const float* __restrict__ We2, const float* __restrict__ be2,
            const float* __restrict__ Wo1, const float* __restrict__ bo1,
            const float* __restrict__ Wo2, const float* __restrict__ bo2,
            const float* __restrict__ Wd1, const float* __restrict__ bd1,
            const float* __restrict__ Wd2, const float* __restrict__ bd2,
            float* __restrict__ out, int Bn, int Tn) {
    __shared__ SM s;
    int tid = threadIdx.x;
    int w = tid >> 5, lane = tid & 31;
    int lq = lane & 3, lr = lane >> 2;

    // ---- scalar staging ----
    for (int i = tid; i < HID * 16; i += 128) s.we2[i] = We2[i];
    for (int i = tid; i < 56; i += 128) {
        s.bo1p[i] = (i < HID) ? bo1[i] : 0.f;
        s.bd1p[i] = (i < HID) ? bd1[i] : 0.f;
        s.wd2p[i] = (i < HID) ? Wd2[i] : 0.f;
    }
    for (int i = tid; i < HID; i += 128) {
        s.be1[i] = be1[i];
        s.w1a[i] = We1[i];
        s.w1b[i] = We1[HID + i];
    }
    for (int i = tid; i < LAT; i += 128) {
        s.bo2[i] = bo2[i];
        s.be2[i] = be2[i];
    }
    for (int i = tid; i < Tn - 1 && i < 128; i += 128)
        s.dt[i] = t[i + 1] - t[i];
    if (tid == 0) s.bd2 = bd2[0];

    // ---- weight fragments (warp 0) ----
    if (w == 0) {
        int n8 = lr;            // column within 8-wide tile
        int k0 = lq * 2;
#pragma unroll
        for (int nt = 0; nt < NT1; nt++) {
            int n = nt * 8 + n8;
            float b0, b1, b2, b3;
            b0 = (n < HID) ? Wo1[(k0)     * HID + n] : 0.f;
            b1 = (n < HID) ? Wo1[(k0 + 1) * HID + n] : 0.f;
            b2 = (n < HID) ? Wo1[(k0 + 8) * HID + n] : 0.f;
            b3 = (n < HID) ? Wo1[(k0 + 9) * HID + n] : 0.f;
            s.B1[nt][lane] = make_uint4(pkhi(b0, b1), pkhi(b2, b3),
                                        pklo(b0, b1), pklo(b2, b3));
            b0 = (n < HID) ? Wd1[(k0)     * HID + n] : 0.f;
            b1 = (n < HID) ? Wd1[(k0 + 1) * HID + n] : 0.f;
            b2 = (n < HID) ? Wd1[(k0 + 8) * HID + n] : 0.f;
            b3 = (n < HID) ? Wd1[(k0 + 9) * HID + n] : 0.f;
            s.BD1[nt][lane] = make_uint4(pkhi(b0, b1), pkhi(b2, b3),
                                         pklo(b0, b1), pklo(b2, b3));
        }
#pragma unroll
        for (int kt = 0; kt < KT2; kt++)
#pragma unroll
            for (int n2 = 0; n2 < 2; n2++) {
                int n = n2 * 8 + n8;
                int kb = kt * 16 + k0;
                float b0 = (kb     < HID) ? Wo2[(kb)     * LAT + n] : 0.f;
                float b1 = (kb + 1 < HID) ? Wo2[(kb + 1) * LAT + n] : 0.f;
                float b2 = (kb + 8 < HID) ? Wo2[(kb + 8) * LAT + n] : 0.f;
                float b3 = (kb + 9 < HID) ? Wo2[(kb + 9) * LAT + n] : 0.f;
                s.B2[kt][n2][lane] = make_uint4(pkhi(b0, b1), pkhi(b2, b3),
                                                pklo(b0, b1), pklo(b2, b3));
            }
    }
    __syncthreads();

    int wbase = (blockIdx.x * 4 + w) * 32;

    // ---- encoder (scalar, one element per lane) ----
    {
        int e = wbase + lane;
        int ce = (e < Bn) ? e : (Bn - 1);
        float xa = x0[2 * ce], xb = x0[2 * ce + 1];
        float z0[16];
#pragma unroll
        for (int j = 0; j < 16; j++) z0[j] = s.be2[j];
#pragma unroll 10
        for (int i = 0; i < HID; i++) {
            float h = fmaxf(fmaf(xb, s.w1b[i], fmaf(xa, s.w1a[i], s.be1[i])), 0.f);
#pragma unroll
            for (int j = 0; j < 16; j++) z0[j] = fmaf(h, s.we2[i * 16 + j], z0[j]);
        }
#pragma unroll
        for (int j = 0; j < 16; j++) s.zst[w][lane][j] = z0[j];
    }
    __syncwarp();

    // gather into D-fragment layout
    float z[16];
#pragma unroll
    for (int m = 0; m < 2; m++)
#pragma unroll
        for (int n2 = 0; n2 < 2; n2++)
#pragma unroll
            for (int j = 0; j < 4; j++) {
                int row = m * 16 + (j >> 1) * 8 + lr;
                int col = n2 * 8 + lq * 2 + (j & 1);
                z[m * 8 + n2 * 4 + j] = s.zst[w][row][col];
            }

    float bo2c[4];
    bo2c[0] = s.bo2[lq * 2];     bo2c[1] = s.bo2[lq * 2 + 1];
    bo2c[2] = s.bo2[8 + lq * 2]; bo2c[3] = s.bo2[8 + lq * 2 + 1];

    dec_eval(z, s, lane, lq, lr, out, wbase, Bn, 0);

    for (int st = 0; st < Tn - 1; ++st) {
        float dtv = s.dt[st];
        float h6 = dtv * (1.f / 6.f);
        float h3 = dtv * (1.f / 3.f);
        float hf = dtv * 0.5f;

        float zn[16], zt[16], kk[16];
#pragma unroll
        for (int j = 0; j < 16; j++) { zn[j] = z[j]; zt[j] = z[j]; }

        for (int stage = 0; stage < 4; ++stage) {
            f_eval(zt, kk, s, lane, lq, bo2c);
            float ws = (stage == 1 || stage == 2) ? h3 : h6;
#pragma unroll
            for (int j = 0; j < 16; j++) zn[j] = fmaf(ws, kk[j], zn[j]);
            if (stage < 3) {
                float as = (stage == 2) ? dtv : hf;
#pragma unroll
                for (int j = 0; j < 16; j++) zt[j] = fmaf(as, kk[j], z[j]);
            }
        }
#pragma unroll
        for (int j = 0; j < 16; j++) z[j] = zn[j];

        dec_eval(z, s, lane, lq, lr, out, wbase, Bn, (size_t)(st + 1) * Bn);
    }
}

extern "C" void kernel_launch(void* const* d_in, const int* in_sizes, int n_in,
                              void* d_out, int out_size) {
    const float* x0  = (const float*)d_in[0];
    const float* t   = (const float*)d_in[1];
    const float* We1 = (const float*)d_in[2];
    const float* be1 = (const float*)d_in[3];
    const float* We2 = (const float*)d_in[4];
    const float* be2 = (const float*)d_in[5];
    const float* Wo1 = (const float*)d_in[6];
    const float* bo1 = (const float*)d_in[7];
    const float* Wo2 = (const float*)d_in[8];
    const float* bo2 = (const float*)d_in[9];
    const float* Wd1 = (const float*)d_in[10];
    const float* bd1 = (const float*)d_in[11];
    const float* Wd2 = (const float*)d_in[12];
    const float* bd2 = (const float*)d_in[13];

    int Bn = in_sizes[0] / 2;
    int Tn = in_sizes[1];

    int blocks = (Bn + 127) / 128;   // 4 warps x 32 elements per CTA
    node_kernel<<<blocks, 128>>>(x0, t, We1, be1, We2, be2, Wo1, bo1,
                                 Wo2, bo2, Wd1, bd1, Wd2, bd2,
                                 (float*)d_out, Bn, Tn);
}